// round 11
// baseline (speedup 1.0000x reference)
#include <cuda_runtime.h>
#include <cuda_fp16.h>
#include <cstdint>

// ---------------------------------------------------------------------------
// AnalogConv2d: 3x3 s1 p1, N=16 C=128 H=W=56 Cout=256, fp32 + bias.
// fp16 mma.sync.m16n8k16 (fp32 accum) implicit GEMM.
// CTA tile 256(Cout) x 128(pos), 8 warps (4Mx2N), warp tile 64x64.
// K = 9 taps * 128 ch, chunk 64 (NCHUNK=18); 4-stage cp.async pipeline.
// R10: x repacked POSITION-MAJOR [img][l][c2] so the B gather is 4 coalesced
// 16B cp.async per thread (was 16 scattered 4B). Swizzle = (pos&7)<<2 (16B-
// granular), conflict-free for both STS and frag LDS.
// ---------------------------------------------------------------------------

#define CIN    128
#define HWD    56
#define LSP    3136
#define COUT   256
#define NIMG   16
#define LTOT   (NIMG * LSP)        // 50176
#define XWORDS (NIMG * LSP * 64)   // 3211264 half2 words
#define TM     256
#define TN     128
#define NCTA   (LTOT / TN)         // 392
#define NCHUNK 18                  // 9 taps * 2 (CHK=64 channels)
#define STAGES 4
#define A_ST_B 32768u              // 256*64*2
#define B_ST_B 16384u              // 128*64*2
#define STG_B  (A_ST_B + B_ST_B)   // 49152
#define SMEMB  (STAGES * STG_B)    // 196608 (192KB)

// Weights fragment-major fp16 pairs: [tap][ck2][mf16][ks4][lane32][4regs]
__device__ __align__(256) uint32_t g_Wh[9 * 2 * 16 * 4 * 32 * 4];
// x packed half2, POSITION-MAJOR: [img][l(3136)][c2(64)]
__device__ __align__(256) uint32_t g_Xh[XWORDS];

__device__ __forceinline__ void cpa16(uint32_t d, const void* s) {
    asm volatile("cp.async.cg.shared.global [%0], [%1], 16;" :: "r"(d), "l"(s));
}
__device__ __forceinline__ void cpa16z(uint32_t d, const void* s, uint32_t sz) {
    // sz = 16 (copy) or 0 (zero-fill, no read)
    asm volatile("cp.async.cg.shared.global [%0], [%1], 16, %2;"
                 :: "r"(d), "l"(s), "r"(sz));
}
__device__ __forceinline__ void mma_f16(float* d, const uint32_t* a,
                                        const uint32_t* b) {
    asm volatile(
        "mma.sync.aligned.m16n8k16.row.col.f32.f16.f16.f32 "
        "{%0,%1,%2,%3}, {%4,%5,%6,%7}, {%8,%9}, {%0,%1,%2,%3};"
        : "+f"(d[0]), "+f"(d[1]), "+f"(d[2]), "+f"(d[3])
        : "r"(a[0]), "r"(a[1]), "r"(a[2]), "r"(a[3]), "r"(b[0]), "r"(b[1]));
}

// ---------------------------------------------------------------------------
// w[co][c][3][3] -> g_Wh fragment-major fp16 pairs.
// idx = ((((tap*2+ck)*16+mf)*4+ks)*32+lane)*4 + r
// m16n8k16 A frag: r0:(g, 2tig) r1:(g+8, 2tig) r2:(g, 2tig+8) r3:(g+8, 2tig+8)
// ---------------------------------------------------------------------------
__global__ void wt_transform_kernel(const float* __restrict__ w) {
    int idx = blockIdx.x * blockDim.x + threadIdx.x;
    if (idx >= 9 * 2 * 16 * 4 * 32 * 4) return;
    int r    = idx & 3;
    int lane = (idx >> 2) & 31;
    int ks   = (idx >> 7) & 3;
    int mf   = (idx >> 9) & 15;
    int ck   = (idx >> 13) & 1;
    int tap  = idx >> 14;
    int g = lane >> 2, tig = lane & 3;
    int co = mf * 16 + g + 8 * (r & 1);
    int c  = ck * 64 + ks * 16 + 2 * tig + 8 * (r >> 1);
    __half2 v = __floats2half2_rn(w[(co * CIN + c) * 9 + tap],
                                  w[(co * CIN + c + 1) * 9 + tap]);
    g_Wh[idx] = *reinterpret_cast<uint32_t*>(&v);
}

// ---------------------------------------------------------------------------
// x fp32 [img][c][l] -> g_Xh half2 [img][l][c2] via tiled smem transpose.
// Block: 64 l-positions x 128 channels. Coalesced reads AND 16B writes.
// ---------------------------------------------------------------------------
__global__ void x_transpose_kernel(const float* __restrict__ x) {
    __shared__ float tile[64 * 133];   // stride 133 -> conflict-free STS
    const int img = blockIdx.y;
    const int lt  = blockIdx.x;        // 0..48
    const int t   = threadIdx.x;

    const float* xs = x + (size_t)img * CIN * LSP + lt * 64;
    #pragma unroll
    for (int i = 0; i < 32; ++i) {
        int idx = i * 256 + t;
        int l = idx & 63, c = idx >> 6;
        tile[l * 133 + c] = xs[(size_t)c * LSP + l];
    }
    __syncthreads();

    const int l = t >> 2, q = t & 3;
    uint32_t* orow = g_Xh + ((size_t)img * LSP + lt * 64 + l) * 64 + q * 16;
    #pragma unroll
    for (int w = 0; w < 4; ++w) {
        uint32_t vr[4];
        #pragma unroll
        for (int j = 0; j < 4; ++j) {
            int c2 = q * 16 + w * 4 + j;
            __half2 h = __floats2half2_rn(tile[l * 133 + 2 * c2],
                                          tile[l * 133 + 2 * c2 + 1]);
            vr[j] = *reinterpret_cast<uint32_t*>(&h);
        }
        uint4 v = { vr[0], vr[1], vr[2], vr[3] };
        *reinterpret_cast<uint4*>(orow + w * 4) = v;
    }
}

// ---------------------------------------------------------------------------
__global__ void __launch_bounds__(256, 1)
conv_mma_kernel(const float* __restrict__ bias,
                float* __restrict__ out) {
    extern __shared__ float smem[];
    uint32_t sb;
    asm("{ .reg .u64 t; cvta.to.shared.u64 t, %1; cvt.u32.u64 %0, t; }"
        : "=r"(sb) : "l"(smem));

    const int tid  = threadIdx.x;
    const int wid  = tid >> 5;
    const int lane = tid & 31;
    const int wm   = wid >> 1;        // 0..3 : 64-row Cout band
    const int wn   = wid & 1;         // 0..1 : 64-col pos band
    const int g    = lane >> 2;
    const int tig  = lane & 3;

    const int l0 = blockIdx.x * TN;

    // ---- B gather setup: thread -> (pos, jbase); 4 x 16B granules ----
    const int pos = tid & 127;
    const int jb  = (tid >> 7) * 4;    // granule base: 0 or 4 (of 8)
    const int l   = l0 + pos;
    const int img = l / LSP;
    const int rl  = l - img * LSP;
    const int oh  = rl / HWD;
    const int ow  = rl - oh * HWD;
    // row base in g_Xh for (img, position): 64 words per position
    const uint32_t* xrow0 = g_Xh + ((size_t)img * LSP) * 64;
    const uint32_t hsw = ((uint32_t)pos & 7u) << 2;   // 16B-granular swizzle
    const uint32_t bdst_row = (uint32_t)pos * 32u;    // 32 words per B row

    float acc[4][8][4];
    #pragma unroll
    for (int mi = 0; mi < 4; ++mi)
        #pragma unroll
        for (int ni = 0; ni < 8; ++ni)
            #pragma unroll
            for (int r2 = 0; r2 < 4; ++r2)
                acc[mi][ni][r2] = 0.0f;

    auto prefetch = [&](int q, int s) {
        const int tap = q >> 1;
        const int ck  = q & 1;
        const int ki  = tap / 3, kj = tap - ki * 3;
        const uint32_t sbase = sb + (uint32_t)s * STG_B;
        // A: 32KB contiguous fragment-major, 8 x 16B per thread
        const uint32_t* asrc = g_Wh + (((size_t)(tap * 2 + ck)) << 13);
        #pragma unroll
        for (int i = 0; i < 8; ++i)
            cpa16(sbase + (uint32_t)(i * 256 + tid) * 16u,
                  asrc + (i * 256 + tid) * 4);
        // B: 4 coalesced 16B granules from the position-major row
        const int ih = oh + ki - 1, iw = ow + kj - 1;
        const bool valid = ((unsigned)ih < HWD) & ((unsigned)iw < HWD);
        const uint32_t* src = valid
            ? (xrow0 + (size_t)(ih * HWD + iw) * 64 + ck * 32 + jb * 4)
            : g_Xh;
        const uint32_t sz = valid ? 16u : 0u;
        const uint32_t bb = sbase + A_ST_B;
        #pragma unroll
        for (int i = 0; i < 4; ++i) {
            uint32_t w4 = (uint32_t)((jb + i) * 4);        // word base of granule
            cpa16z(bb + (bdst_row + (w4 ^ hsw)) * 4u, src + i * 4, sz);
        }
    };

    auto compute = [&](int s) {
        const uint4*    A4 = (const uint4*)(smem + s * (STG_B / 4));
        const uint32_t* Bb = (const uint32_t*)(smem + s * (STG_B / 4)
                                               + (A_ST_B / 4));
        const uint32_t g4 = (uint32_t)g << 2;

        uint4    af[2][4];
        uint32_t bf[2][8][2];
        auto ldf = [&](int ks, int b) {
            #pragma unroll
            for (int mi = 0; mi < 4; ++mi)
                af[b][mi] = A4[((wm * 4 + mi) * 4 + ks) * 32 + lane];
            #pragma unroll
            for (int ni = 0; ni < 8; ++ni) {
                const uint32_t row = (uint32_t)(wn * 64 + ni * 8 + g) * 32u;
                const uint32_t k0  = (uint32_t)(ks * 8 + tig);
                bf[b][ni][0] = Bb[row + (k0 ^ g4)];
                bf[b][ni][1] = Bb[row + ((k0 + 4) ^ g4)];
            }
        };

        ldf(0, 0);
        #pragma unroll
        for (int ks = 0; ks < 4; ++ks) {
            const int cur = ks & 1;
            if (ks < 3) ldf(ks + 1, cur ^ 1);
            #pragma unroll
            for (int mi = 0; mi < 4; ++mi) {
                uint32_t a_[4] = { af[cur][mi].x, af[cur][mi].y,
                                   af[cur][mi].z, af[cur][mi].w };
                #pragma unroll
                for (int ni = 0; ni < 8; ++ni)
                    mma_f16(acc[mi][ni], a_, bf[cur][ni]);
            }
        }
    };

    // ---- 4-stage pipeline, one sync per chunk ----
    #pragma unroll
    for (int s = 0; s < STAGES - 1; ++s) {
        prefetch(s, s);
        asm volatile("cp.async.commit_group;" ::: "memory");
    }
    #pragma unroll 1
    for (int q = 0; q < NCHUNK; ++q) {
        asm volatile("cp.async.wait_group %0;" :: "n"(STAGES - 2) : "memory");
        __syncthreads();   // stage q&3 visible; slot (q+3)&3 free to refill
        if (q + STAGES - 1 < NCHUNK)
            prefetch(q + STAGES - 1, (q + STAGES - 1) & (STAGES - 1));
        asm volatile("cp.async.commit_group;" ::: "memory");
        compute(q & (STAGES - 1));
    }

    // ---- epilogue: +bias, float2 stores ----
    const int co_base = wm * 64 + g;
    float bv[4][2];
    #pragma unroll
    for (int mi = 0; mi < 4; ++mi) {
        bv[mi][0] = bias[co_base + mi * 16];
        bv[mi][1] = bias[co_base + mi * 16 + 8];
    }
    #pragma unroll
    for (int ni = 0; ni < 8; ++ni) {
        const int le  = l0 + wn * 64 + ni * 8 + 2 * tig;
        const int im2 = le / LSP;
        const int rle = le - im2 * LSP;
        float* ob = out + (size_t)im2 * COUT * LSP + rle;
        #pragma unroll
        for (int mi = 0; mi < 4; ++mi) {
            #pragma unroll
            for (int h = 0; h < 2; ++h) {
                const int co = co_base + mi * 16 + h * 8;
                float2 v;
                v.x = acc[mi][ni][h * 2 + 0] + bv[mi][h];
                v.y = acc[mi][ni][h * 2 + 1] + bv[mi][h];
                *reinterpret_cast<float2*>(ob + (size_t)co * LSP) = v;
            }
        }
    }
}

// ---------------------------------------------------------------------------
extern "C" void kernel_launch(void* const* d_in, const int* in_sizes, int n_in,
                              void* d_out, int out_size) {
    const float* x    = (const float*)d_in[0];
    const float* w    = (const float*)d_in[1];
    const float* bias = (const float*)d_in[2];
    float* out = (float*)d_out;

    cudaFuncSetAttribute(conv_mma_kernel,
                         cudaFuncAttributeMaxDynamicSharedMemorySize, SMEMB);

    wt_transform_kernel<<<(9 * 2 * 16 * 4 * 32 * 4 + 255) / 256, 256>>>(w);
    dim3 tgrid(LSP / 64, NIMG, 1);     // 49 x 16
    x_transpose_kernel<<<tgrid, 256>>>(x);
    conv_mma_kernel<<<NCTA, 256, SMEMB>>>(bias, out);
}

// round 12
// speedup vs baseline: 1.0582x; 1.0582x over previous
#include <cuda_runtime.h>
#include <cuda_fp16.h>
#include <cstdint>

// ---------------------------------------------------------------------------
// AnalogConv2d: 3x3 s1 p1, N=16 C=128 H=W=56 Cout=256, fp32 + bias.
// fp16 mma.sync.m16n8k16 (fp32 accum) implicit GEMM.
// CTA tile 256(Cout) x 128(pos), 8 warps (4Mx2N), warp tile 64x64.
// K = 9 taps * 128 ch, chunk 64 (NCHUNK=18); 4-stage cp.async pipeline.
// R11 (base = R9, best): x packed as 8-channel 16B granules [img][c8][l]
// -> B gather is 4 x 16B coalesced cp.async/thread; B fragments loaded by
// ldmatrix.x4 (16 instr/warp-chunk vs 64 LDS.32 + XOR math). 16B-granule
// swizzle gi ^= (pos&7): conflict-free STS AND ldmatrix, order-preserving.
// ---------------------------------------------------------------------------

#define CIN    128
#define HWD    56
#define LSP    3136
#define COUT   256
#define NIMG   16
#define LTOT   (NIMG * LSP)        // 50176
#define X4N    (NIMG * 16 * LSP)   // 802816 uint4 granules (8 ch each)
#define TM     256
#define TN     128
#define NCTA   (LTOT / TN)         // 392
#define NCHUNK 18                  // 9 taps * 2 (CHK=64 channels)
#define STAGES 4
#define A_ST_B 32768u              // 256*64*2
#define B_ST_B 16384u              // 128*64*2
#define STG_B  (A_ST_B + B_ST_B)   // 49152
#define SMEMB  (STAGES * STG_B)    // 196608 (192KB)

// Weights fragment-major fp16 pairs: [tap][ck2][mf16][ks4][lane32][4regs]
__device__ __align__(256) uint32_t g_Wh[9 * 2 * 16 * 4 * 32 * 4];
// x packed 8-channel fp16 granules: [img][c8(16)][l(3136)], one uint4 each
__device__ __align__(256) uint4 g_X4[X4N];

__device__ __forceinline__ void cpa16(uint32_t d, const void* s) {
    asm volatile("cp.async.cg.shared.global [%0], [%1], 16;" :: "r"(d), "l"(s));
}
__device__ __forceinline__ void cpa16z(uint32_t d, const void* s, uint32_t sz) {
    asm volatile("cp.async.cg.shared.global [%0], [%1], 16, %2;"
                 :: "r"(d), "l"(s), "r"(sz));
}
__device__ __forceinline__ void mma_f16(float* d, const uint32_t* a,
                                        const uint32_t* b) {
    asm volatile(
        "mma.sync.aligned.m16n8k16.row.col.f32.f16.f16.f32 "
        "{%0,%1,%2,%3}, {%4,%5,%6,%7}, {%8,%9}, {%0,%1,%2,%3};"
        : "+f"(d[0]), "+f"(d[1]), "+f"(d[2]), "+f"(d[3])
        : "r"(a[0]), "r"(a[1]), "r"(a[2]), "r"(a[3]), "r"(b[0]), "r"(b[1]));
}
__device__ __forceinline__ void ldmx4(uint32_t& r0, uint32_t& r1,
                                      uint32_t& r2, uint32_t& r3, uint32_t a) {
    asm volatile("ldmatrix.sync.aligned.m8n8.x4.shared.b16 {%0,%1,%2,%3}, [%4];"
                 : "=r"(r0), "=r"(r1), "=r"(r2), "=r"(r3) : "r"(a));
}

// ---------------------------------------------------------------------------
// w[co][c][3][3] -> g_Wh fragment-major fp16 pairs.
// idx = ((((tap*2+ck)*16+mf)*4+ks)*32+lane)*4 + r
// m16n8k16 A frag: r0:(g, 2tig) r1:(g+8, 2tig) r2:(g, 2tig+8) r3:(g+8, 2tig+8)
// ---------------------------------------------------------------------------
__global__ void wt_transform_kernel(const float* __restrict__ w) {
    int idx = blockIdx.x * blockDim.x + threadIdx.x;
    if (idx >= 9 * 2 * 16 * 4 * 32 * 4) return;
    int r    = idx & 3;
    int lane = (idx >> 2) & 31;
    int ks   = (idx >> 7) & 3;
    int mf   = (idx >> 9) & 15;
    int ck   = (idx >> 13) & 1;
    int tap  = idx >> 14;
    int g = lane >> 2, tig = lane & 3;
    int co = mf * 16 + g + 8 * (r & 1);
    int c  = ck * 64 + ks * 16 + 2 * tig + 8 * (r >> 1);
    __half2 v = __floats2half2_rn(w[(co * CIN + c) * 9 + tap],
                                  w[(co * CIN + c + 1) * 9 + tap]);
    g_Wh[idx] = *reinterpret_cast<uint32_t*>(&v);
}

// x fp32 [img][c][l] -> g_X4 [img][c8][l]: 8 consecutive channels per 16B.
__global__ void x_pack_kernel(const float* __restrict__ x) {
    int i = blockIdx.x * blockDim.x + threadIdx.x;
    if (i >= X4N) return;
    int l  = i % LSP;
    int t  = i / LSP;
    int c8 = t & 15;
    int im = t >> 4;
    const float* p = x + ((size_t)im * CIN + c8 * 8) * LSP + l;
    uint32_t wds[4];
    #pragma unroll
    for (int j = 0; j < 4; ++j) {
        __half2 h = __floats2half2_rn(p[(size_t)(2 * j) * LSP],
                                      p[(size_t)(2 * j + 1) * LSP]);
        wds[j] = *reinterpret_cast<uint32_t*>(&h);
    }
    uint4 v = { wds[0], wds[1], wds[2], wds[3] };
    g_X4[i] = v;
}

// ---------------------------------------------------------------------------
__global__ void __launch_bounds__(256, 1)
conv_mma_kernel(const float* __restrict__ bias,
                float* __restrict__ out) {
    extern __shared__ float smem[];
    uint32_t sb;
    asm("{ .reg .u64 t; cvta.to.shared.u64 t, %1; cvt.u32.u64 %0, t; }"
        : "=r"(sb) : "l"(smem));

    const int tid  = threadIdx.x;
    const int wid  = tid >> 5;
    const int lane = tid & 31;
    const int wm   = wid >> 1;        // 0..3 : 64-row Cout band
    const int wn   = wid & 1;         // 0..1 : 64-col pos band

    const int l0 = blockIdx.x * TN;

    // ---- B gather setup: thread -> (pos, jb); 4 x 16B granules each ----
    const int pos = tid & 127;
    const int jb  = (tid >> 7) * 4;    // granule base within chunk: 0 or 4
    const int l   = l0 + pos;
    const int img = l / LSP;
    const int rl  = l - img * LSP;
    const int oh  = rl / HWD;
    const int ow  = rl - oh * HWD;
    const uint4* xb = g_X4 + (size_t)img * 16 * LSP;
    const uint32_t hsw3 = (uint32_t)pos & 7u;
    const uint32_t bdst_row = (uint32_t)pos * 32u;   // words per B row

    // ---- ldmatrix lane address precompute ----
    // tile t = lane>>3 maps to (ni offset = (t>>1), k-half h = t&1), row r.
    const int lt = lane >> 3;
    const int lr = lane & 7;
    const int lh = lt & 1;
    const uint32_t lanebase =
        (uint32_t)(wn * 64 + (lt >> 1) * 8 + lr) * 128u;   // bytes
    // per-(ks): granule = (2ks + lh) ^ lr, byte offset = granule<<4

    float acc[4][8][4];
    #pragma unroll
    for (int mi = 0; mi < 4; ++mi)
        #pragma unroll
        for (int ni = 0; ni < 8; ++ni)
            #pragma unroll
            for (int r2 = 0; r2 < 4; ++r2)
                acc[mi][ni][r2] = 0.0f;

    auto prefetch = [&](int q, int s) {
        const int tap = q >> 1;
        const int ck  = q & 1;
        const int ki  = tap / 3, kj = tap - ki * 3;
        const uint32_t sbase = sb + (uint32_t)s * STG_B;
        // A: 32KB contiguous fragment-major, 8 x 16B per thread
        const uint32_t* asrc = g_Wh + (((size_t)(tap * 2 + ck)) << 13);
        #pragma unroll
        for (int i = 0; i < 8; ++i)
            cpa16(sbase + (uint32_t)(i * 256 + tid) * 16u,
                  asrc + (i * 256 + tid) * 4);
        // B: 4 x 16B granules (8 channels each), coalesced across pos
        const int ih = oh + ki - 1, iw = ow + kj - 1;
        const bool valid = ((unsigned)ih < HWD) & ((unsigned)iw < HWD);
        const uint4* src = valid
            ? (xb + (size_t)(ck * 8 + jb) * LSP + ih * HWD + iw)
            : g_X4;
        const uint32_t sz = valid ? 16u : 0u;
        const uint32_t bb = sbase + A_ST_B;
        #pragma unroll
        for (int i = 0; i < 4; ++i) {
            uint32_t gi = (uint32_t)(jb + i);
            cpa16z(bb + (bdst_row + ((gi ^ hsw3) << 2)) * 4u,
                   src + (size_t)i * LSP, sz);
        }
    };

    auto compute = [&](int s) {
        const uint4* A4 = (const uint4*)(smem + s * (STG_B / 4));
        const uint32_t bB = sb + (uint32_t)s * STG_B + A_ST_B + lanebase;

        uint4    af[2][4];
        uint32_t bf[2][8][2];
        auto ldf = [&](int ks, int b) {
            #pragma unroll
            for (int mi = 0; mi < 4; ++mi)
                af[b][mi] = A4[((wm * 4 + mi) * 4 + ks) * 32 + lane];
            const uint32_t goff =
                (uint32_t)(((2 * ks + lh) ^ lr) << 4);
            #pragma unroll
            for (int p = 0; p < 4; ++p)
                ldmx4(bf[b][p * 2][0], bf[b][p * 2][1],
                      bf[b][p * 2 + 1][0], bf[b][p * 2 + 1][1],
                      bB + (uint32_t)p * 2048u + goff);
        };

        ldf(0, 0);
        #pragma unroll
        for (int ks = 0; ks < 4; ++ks) {
            const int cur = ks & 1;
            if (ks < 3) ldf(ks + 1, cur ^ 1);
            #pragma unroll
            for (int mi = 0; mi < 4; ++mi) {
                uint32_t a_[4] = { af[cur][mi].x, af[cur][mi].y,
                                   af[cur][mi].z, af[cur][mi].w };
                #pragma unroll
                for (int ni = 0; ni < 8; ++ni)
                    mma_f16(acc[mi][ni], a_, bf[cur][ni]);
            }
        }
    };

    // ---- 4-stage pipeline, one sync per chunk ----
    #pragma unroll
    for (int s = 0; s < STAGES - 1; ++s) {
        prefetch(s, s);
        asm volatile("cp.async.commit_group;" ::: "memory");
    }
    #pragma unroll 1
    for (int q = 0; q < NCHUNK; ++q) {
        asm volatile("cp.async.wait_group %0;" :: "n"(STAGES - 2) : "memory");
        __syncthreads();   // stage q&3 visible; slot (q+3)&3 free to refill
        if (q + STAGES - 1 < NCHUNK)
            prefetch(q + STAGES - 1, (q + STAGES - 1) & (STAGES - 1));
        asm volatile("cp.async.commit_group;" ::: "memory");
        compute(q & (STAGES - 1));
    }

    // ---- epilogue: +bias, float2 stores ----
    const int g   = lane >> 2;
    const int tig = lane & 3;
    const int co_base = wm * 64 + g;
    float bv[4][2];
    #pragma unroll
    for (int mi = 0; mi < 4; ++mi) {
        bv[mi][0] = bias[co_base + mi * 16];
        bv[mi][1] = bias[co_base + mi * 16 + 8];
    }
    #pragma unroll
    for (int ni = 0; ni < 8; ++ni) {
        const int le  = l0 + wn * 64 + ni * 8 + 2 * tig;
        const int im2 = le / LSP;
        const int rle = le - im2 * LSP;
        float* ob = out + (size_t)im2 * COUT * LSP + rle;
        #pragma unroll
        for (int mi = 0; mi < 4; ++mi) {
            #pragma unroll
            for (int h = 0; h < 2; ++h) {
                const int co = co_base + mi * 16 + h * 8;
                float2 v;
                v.x = acc[mi][ni][h * 2 + 0] + bv[mi][h];
                v.y = acc[mi][ni][h * 2 + 1] + bv[mi][h];
                *reinterpret_cast<float2*>(ob + (size_t)co * LSP) = v;
            }
        }
    }
}

// ---------------------------------------------------------------------------
extern "C" void kernel_launch(void* const* d_in, const int* in_sizes, int n_in,
                              void* d_out, int out_size) {
    const float* x    = (const float*)d_in[0];
    const float* w    = (const float*)d_in[1];
    const float* bias = (const float*)d_in[2];
    float* out = (float*)d_out;

    cudaFuncSetAttribute(conv_mma_kernel,
                         cudaFuncAttributeMaxDynamicSharedMemorySize, SMEMB);

    wt_transform_kernel<<<(9 * 2 * 16 * 4 * 32 * 4 + 255) / 256, 256>>>(w);
    x_pack_kernel<<<(X4N + 255) / 256, 256>>>(x);
    conv_mma_kernel<<<NCTA, 256, SMEMB>>>(bias, out);
}

// round 13
// speedup vs baseline: 1.1227x; 1.0609x over previous
#include <cuda_runtime.h>
#include <cuda_fp16.h>
#include <cstdint>

// ---------------------------------------------------------------------------
// AnalogConv2d: 3x3 s1 p1, N=16 C=128 H=W=56 Cout=256, fp32 + bias.
// fp16 mma.sync.m16n8k16 (fp32 accum) implicit GEMM.
// R12: CTA tile 256(Cout) x 128(pos), 512 threads, 16 warps (4Mx4N),
// warp tile 64x32 -> 4 warps/SMSP (retry of R5's lever in the fp16+ldmatrix
// regime where its LDS/issue taxes are gone). Regs budgeted <=128:
// acc 64 + A frags single-buffered + B frags double-buffered.
// K = 9 taps * 128 ch, chunk 64 (NCHUNK=18); 4-stage cp.async pipeline.
// Transforms fused into one kernel.
// ---------------------------------------------------------------------------

#define CIN    128
#define HWD    56
#define LSP    3136
#define COUT   256
#define NIMG   16
#define LTOT   (NIMG * LSP)        // 50176
#define X4N    (NIMG * 16 * LSP)   // 802816 uint4 granules (8 ch each)
#define WT_N   (9 * 2 * 16 * 4 * 32 * 4)   // 147456
#define TM     256
#define TN     128
#define NCTA   (LTOT / TN)         // 392
#define NCHUNK 18                  // 9 taps * 2 (CHK=64 channels)
#define STAGES 4
#define A_ST_B 32768u              // 256*64*2
#define B_ST_B 16384u              // 128*64*2
#define STG_B  (A_ST_B + B_ST_B)   // 49152
#define SMEMB  (STAGES * STG_B)    // 196608 (192KB)

// Weights fragment-major fp16 pairs: [tap][ck2][mf16][ks4][lane32][4regs]
__device__ __align__(256) uint32_t g_Wh[WT_N];
// x packed 8-channel fp16 granules: [img][c8(16)][l(3136)], one uint4 each
__device__ __align__(256) uint4 g_X4[X4N];

__device__ __forceinline__ void cpa16(uint32_t d, const void* s) {
    asm volatile("cp.async.cg.shared.global [%0], [%1], 16;" :: "r"(d), "l"(s));
}
__device__ __forceinline__ void cpa16z(uint32_t d, const void* s, uint32_t sz) {
    asm volatile("cp.async.cg.shared.global [%0], [%1], 16, %2;"
                 :: "r"(d), "l"(s), "r"(sz));
}
__device__ __forceinline__ void mma_f16(float* d, const uint32_t* a,
                                        const uint32_t* b) {
    asm volatile(
        "mma.sync.aligned.m16n8k16.row.col.f32.f16.f16.f32 "
        "{%0,%1,%2,%3}, {%4,%5,%6,%7}, {%8,%9}, {%0,%1,%2,%3};"
        : "+f"(d[0]), "+f"(d[1]), "+f"(d[2]), "+f"(d[3])
        : "r"(a[0]), "r"(a[1]), "r"(a[2]), "r"(a[3]), "r"(b[0]), "r"(b[1]));
}
__device__ __forceinline__ void ldmx4(uint32_t& r0, uint32_t& r1,
                                      uint32_t& r2, uint32_t& r3, uint32_t a) {
    asm volatile("ldmatrix.sync.aligned.m8n8.x4.shared.b16 {%0,%1,%2,%3}, [%4];"
                 : "=r"(r0), "=r"(r1), "=r"(r2), "=r"(r3) : "r"(a));
}

// ---------------------------------------------------------------------------
// Fused transform: x fp32 [img][c][l] -> g_X4 [img][c8][l] (8ch granules)
// and w[co][c][3][3] -> g_Wh fragment-major fp16 pairs.
// ---------------------------------------------------------------------------
__global__ void transform_kernel(const float* __restrict__ x,
                                 const float* __restrict__ w) {
    int i = blockIdx.x * blockDim.x + threadIdx.x;
    if (i < X4N) {
        int l  = i % LSP;
        int t  = i / LSP;
        int c8 = t & 15;
        int im = t >> 4;
        const float* p = x + ((size_t)im * CIN + c8 * 8) * LSP + l;
        uint32_t wds[4];
        #pragma unroll
        for (int j = 0; j < 4; ++j) {
            __half2 h = __floats2half2_rn(p[(size_t)(2 * j) * LSP],
                                          p[(size_t)(2 * j + 1) * LSP]);
            wds[j] = *reinterpret_cast<uint32_t*>(&h);
        }
        uint4 v = { wds[0], wds[1], wds[2], wds[3] };
        g_X4[i] = v;
    } else {
        int idx = i - X4N;
        if (idx >= WT_N) return;
        int r    = idx & 3;
        int lane = (idx >> 2) & 31;
        int ks   = (idx >> 7) & 3;
        int mf   = (idx >> 9) & 15;
        int ck   = (idx >> 13) & 1;
        int tap  = idx >> 14;
        int g = lane >> 2, tig = lane & 3;
        int co = mf * 16 + g + 8 * (r & 1);
        int c  = ck * 64 + ks * 16 + 2 * tig + 8 * (r >> 1);
        __half2 v = __floats2half2_rn(w[(co * CIN + c) * 9 + tap],
                                      w[(co * CIN + c + 1) * 9 + tap]);
        g_Wh[idx] = *reinterpret_cast<uint32_t*>(&v);
    }
}

// ---------------------------------------------------------------------------
__global__ void __launch_bounds__(512, 1)
conv_mma_kernel(const float* __restrict__ bias,
                float* __restrict__ out) {
    extern __shared__ float smem[];
    uint32_t sb;
    asm("{ .reg .u64 t; cvta.to.shared.u64 t, %1; cvt.u32.u64 %0, t; }"
        : "=r"(sb) : "l"(smem));

    const int tid  = threadIdx.x;
    const int wid  = tid >> 5;
    const int lane = tid & 31;
    const int wm   = wid >> 2;        // 0..3 : 64-row Cout band
    const int wn   = wid & 3;         // 0..3 : 32-col pos band

    const int l0 = blockIdx.x * TN;

    // ---- B gather setup: thread -> (pos, jb); 2 x 16B granules each ----
    const int pos = tid & 127;
    const int jb  = (tid >> 7) * 2;    // granule base within chunk: 0,2,4,6
    const int l   = l0 + pos;
    const int img = l / LSP;
    const int rl  = l - img * LSP;
    const int oh  = rl / HWD;
    const int ow  = rl - oh * HWD;
    const uint4* xb = g_X4 + (size_t)img * 16 * LSP;
    const uint32_t hsw3 = (uint32_t)pos & 7u;
    const uint32_t bdst_row = (uint32_t)pos * 32u;   // words per B row

    // ---- ldmatrix lane address precompute ----
    const int lt = lane >> 3;          // tile 0..3 within one ldmx4
    const int lr = lane & 7;           // row within m8 tile
    const int lh = lt & 1;             // k-half
    const uint32_t lanebase =
        (uint32_t)(wn * 32 + (lt >> 1) * 8 + lr) * 128u;   // bytes

    float acc[4][4][4];
    #pragma unroll
    for (int mi = 0; mi < 4; ++mi)
        #pragma unroll
        for (int ni = 0; ni < 4; ++ni)
            #pragma unroll
            for (int r2 = 0; r2 < 4; ++r2)
                acc[mi][ni][r2] = 0.0f;

    auto prefetch = [&](int q, int s) {
        const int tap = q >> 1;
        const int ck  = q & 1;
        const int ki  = tap / 3, kj = tap - ki * 3;
        const uint32_t sbase = sb + (uint32_t)s * STG_B;
        // A: 32KB contiguous fragment-major, 4 x 16B per thread
        const uint32_t* asrc = g_Wh + (((size_t)(tap * 2 + ck)) << 13);
        #pragma unroll
        for (int i = 0; i < 4; ++i)
            cpa16(sbase + (uint32_t)(i * 512 + tid) * 16u,
                  asrc + (i * 512 + tid) * 4);
        // B: 2 x 16B granules (8 channels each), coalesced across pos
        const int ih = oh + ki - 1, iw = ow + kj - 1;
        const bool valid = ((unsigned)ih < HWD) & ((unsigned)iw < HWD);
        const uint4* src = valid
            ? (xb + (size_t)(ck * 8 + jb) * LSP + ih * HWD + iw)
            : g_X4;
        const uint32_t sz = valid ? 16u : 0u;
        const uint32_t bb = sbase + A_ST_B;
        #pragma unroll
        for (int i = 0; i < 2; ++i) {
            uint32_t gi = (uint32_t)(jb + i);
            cpa16z(bb + (bdst_row + ((gi ^ hsw3) << 2)) * 4u,
                   src + (size_t)i * LSP, sz);
        }
    };

    auto compute = [&](int s) {
        const uint4* A4 = (const uint4*)(smem + s * (STG_B / 4));
        const uint32_t bB = sb + (uint32_t)s * STG_B + A_ST_B + lanebase;

        uint32_t bf[2][4][2];
        auto ldmB = [&](int ks, int b) {
            const uint32_t goff = (uint32_t)(((2 * ks + lh) ^ lr) << 4);
            #pragma unroll
            for (int p = 0; p < 2; ++p)
                ldmx4(bf[b][p * 2][0], bf[b][p * 2][1],
                      bf[b][p * 2 + 1][0], bf[b][p * 2 + 1][1],
                      bB + (uint32_t)p * 2048u + goff);
        };

        ldmB(0, 0);
        #pragma unroll
        for (int ks = 0; ks < 4; ++ks) {
            const int cur = ks & 1;
            if (ks < 3) ldmB(ks + 1, cur ^ 1);
            uint4 af[4];
            #pragma unroll
            for (int mi = 0; mi < 4; ++mi)
                af[mi] = A4[((wm * 4 + mi) * 4 + ks) * 32 + lane];
            #pragma unroll
            for (int mi = 0; mi < 4; ++mi) {
                uint32_t a_[4] = { af[mi].x, af[mi].y, af[mi].z, af[mi].w };
                #pragma unroll
                for (int ni = 0; ni < 4; ++ni)
                    mma_f16(acc[mi][ni], a_, bf[cur][ni]);
            }
        }
    };

    // ---- 4-stage pipeline, one sync per chunk ----
    #pragma unroll
    for (int s = 0; s < STAGES - 1; ++s) {
        prefetch(s, s);
        asm volatile("cp.async.commit_group;" ::: "memory");
    }
    #pragma unroll 1
    for (int q = 0; q < NCHUNK; ++q) {
        asm volatile("cp.async.wait_group %0;" :: "n"(STAGES - 2) : "memory");
        __syncthreads();   // stage q&3 visible; slot (q+3)&3 free to refill
        if (q + STAGES - 1 < NCHUNK)
            prefetch(q + STAGES - 1, (q + STAGES - 1) & (STAGES - 1));
        asm volatile("cp.async.commit_group;" ::: "memory");
        compute(q & (STAGES - 1));
    }

    // ---- epilogue: +bias, float2 stores ----
    const int g   = lane >> 2;
    const int tig = lane & 3;
    const int co_base = wm * 64 + g;
    float bv[4][2];
    #pragma unroll
    for (int mi = 0; mi < 4; ++mi) {
        bv[mi][0] = bias[co_base + mi * 16];
        bv[mi][1] = bias[co_base + mi * 16 + 8];
    }
    #pragma unroll
    for (int ni = 0; ni < 4; ++ni) {
        const int le  = l0 + wn * 32 + ni * 8 + 2 * tig;
        const int im2 = le / LSP;
        const int rle = le - im2 * LSP;
        float* ob = out + (size_t)im2 * COUT * LSP + rle;
        #pragma unroll
        for (int mi = 0; mi < 4; ++mi) {
            #pragma unroll
            for (int h = 0; h < 2; ++h) {
                const int co = co_base + mi * 16 + h * 8;
                float2 v;
                v.x = acc[mi][ni][h * 2 + 0] + bv[mi][h];
                v.y = acc[mi][ni][h * 2 + 1] + bv[mi][h];
                *reinterpret_cast<float2*>(ob + (size_t)co * LSP) = v;
            }
        }
    }
}

// ---------------------------------------------------------------------------
extern "C" void kernel_launch(void* const* d_in, const int* in_sizes, int n_in,
                              void* d_out, int out_size) {
    const float* x    = (const float*)d_in[0];
    const float* w    = (const float*)d_in[1];
    const float* bias = (const float*)d_in[2];
    float* out = (float*)d_out;

    cudaFuncSetAttribute(conv_mma_kernel,
                         cudaFuncAttributeMaxDynamicSharedMemorySize, SMEMB);

    transform_kernel<<<(X4N + WT_N + 255) / 256, 256>>>(x, w);
    conv_mma_kernel<<<NCTA, 512, SMEMB>>>(bias, out);
}